// round 4
// baseline (speedup 1.0000x reference)
#include <cuda_runtime.h>
#include <cuda_bf16.h>
#include <math.h>

// Problem constants (fixed by the dataset)
#define N_NODES  50000
#define N_EDGES  1600000
#define D_FEAT   512
#define HIDDEN   128
#define N_CLS    32

// ---------------- device scratch (no allocs allowed) ----------------
__device__ __align__(256) float g_deg [N_NODES];                  // deg -> dinv (in place)
__device__ __align__(256) float g_h1  [(size_t)N_NODES * HIDDEN]; // x @ W1
__device__ __align__(256) float g_agg1[(size_t)N_NODES * HIDDEN]; // aggregated layer-1
__device__ __align__(256) float g_h2  [(size_t)N_NODES * N_CLS];  // relu(agg1+b1) @ W2

// ---------------- kernels ----------------

// Zero accumulators, set deg = 1 (self-loop contribution).
__global__ void k_init(float* __restrict__ out) {
    int i = blockIdx.x * blockDim.x + threadIdx.x;
    int stride = gridDim.x * blockDim.x;
    for (int j = i; j < N_NODES; j += stride) g_deg[j] = 1.0f;
    for (size_t j = i; j < (size_t)N_NODES * HIDDEN; j += stride) g_agg1[j] = 0.0f;
    for (size_t j = i; j < (size_t)N_NODES * N_CLS; j += stride) out[j] = 0.0f;
}

// deg[dst] += 1 per edge  (edge_index is INT32: jax x64 is disabled)
__global__ void k_deg(const int* __restrict__ dst, int E) {
    int e = blockIdx.x * blockDim.x + threadIdx.x;
    if (e < E) atomicAdd(&g_deg[dst[e]], 1.0f);
}

// deg -> rsqrt(deg)
__global__ void k_dinv() {
    int i = blockIdx.x * blockDim.x + threadIdx.x;
    if (i < N_NODES) g_deg[i] = rsqrtf(g_deg[i]);
}

// h1 = x @ W1   (M=N_NODES, K=512, N=128)  classic 128x128x8 fp32 tiled SGEMM
#define BM 128
#define BN 128
#define BK 8
__global__ __launch_bounds__(256) void k_gemm1(const float* __restrict__ A,
                                               const float* __restrict__ B) {
    __shared__ float As[BK][BM];
    __shared__ float Bs[BK][BN];
    const int tid = threadIdx.x;
    const int row0 = blockIdx.x * BM;
    const int tx = tid % 16;          // 16x16 thread grid, 8x8 micro-tile
    const int ty = tid / 16;

    const int arow = tid >> 1, acol = (tid & 1) * 4;   // A: 128 rows x 8 cols (2 float4/row)
    const int brow = tid >> 5, bcol = (tid & 31) * 4;  // B: 8 rows x 128 cols

    float acc[8][8];
    #pragma unroll
    for (int i = 0; i < 8; i++)
        #pragma unroll
        for (int j = 0; j < 8; j++) acc[i][j] = 0.0f;

    for (int k0 = 0; k0 < D_FEAT; k0 += BK) {
        float4 a = make_float4(0.f, 0.f, 0.f, 0.f);
        const int gr = row0 + arow;
        if (gr < N_NODES)
            a = *(const float4*)(A + (size_t)gr * D_FEAT + k0 + acol);
        As[acol + 0][arow] = a.x;
        As[acol + 1][arow] = a.y;
        As[acol + 2][arow] = a.z;
        As[acol + 3][arow] = a.w;

        float4 b = *(const float4*)(B + (size_t)(k0 + brow) * HIDDEN + bcol);
        Bs[brow][bcol + 0] = b.x;
        Bs[brow][bcol + 1] = b.y;
        Bs[brow][bcol + 2] = b.z;
        Bs[brow][bcol + 3] = b.w;
        __syncthreads();

        #pragma unroll
        for (int k = 0; k < BK; k++) {
            float ra[8], rb[8];
            #pragma unroll
            for (int i = 0; i < 8; i++) ra[i] = As[k][ty * 8 + i];
            #pragma unroll
            for (int j = 0; j < 8; j++) rb[j] = Bs[k][tx * 8 + j];
            #pragma unroll
            for (int i = 0; i < 8; i++)
                #pragma unroll
                for (int j = 0; j < 8; j++)
                    acc[i][j] = fmaf(ra[i], rb[j], acc[i][j]);
        }
        __syncthreads();
    }

    #pragma unroll
    for (int i = 0; i < 8; i++) {
        const int gr = row0 + ty * 8 + i;
        if (gr < N_NODES) {
            float4* cp = (float4*)(g_h1 + (size_t)gr * HIDDEN + tx * 8);
            cp[0] = make_float4(acc[i][0], acc[i][1], acc[i][2], acc[i][3]);
            cp[1] = make_float4(acc[i][4], acc[i][5], acc[i][6], acc[i][7]);
        }
    }
}

// Layer-1 aggregation: warp per (edge | self-loop), scalar fp32 atomics
__global__ void k_scatter1(const int* __restrict__ src,
                           const int* __restrict__ dst, int E) {
    const int warp = (blockIdx.x * blockDim.x + threadIdx.x) >> 5;
    const int lane = threadIdx.x & 31;
    if (warp >= E + N_NODES) return;
    int s, d; float norm;
    if (warp < E) {
        s = src[warp];
        d = dst[warp];
        norm = g_deg[s] * g_deg[d];       // g_deg holds dinv now
    } else {
        s = d = warp - E;
        const float v = g_deg[s];
        norm = v * v;
    }
    float4 v = *(const float4*)(g_h1 + (size_t)s * HIDDEN + lane * 4);
    float* o = g_agg1 + (size_t)d * HIDDEN + lane * 4;
    atomicAdd(o + 0, v.x * norm);
    atomicAdd(o + 1, v.y * norm);
    atomicAdd(o + 2, v.z * norm);
    atomicAdd(o + 3, v.w * norm);
}

// h2 = relu(agg1 + b1) @ W2   (warp per node; W2 is [128,32] row-major)
__global__ void k_gemm2(const float* __restrict__ b1, const float* __restrict__ W2) {
    const int node = (blockIdx.x * blockDim.x + threadIdx.x) >> 5;
    const int lane = threadIdx.x & 31;
    if (node >= N_NODES) return;
    float r[4];
    #pragma unroll
    for (int c = 0; c < 4; c++) {
        const int k = c * 32 + lane;
        r[c] = fmaxf(g_agg1[(size_t)node * HIDDEN + k] + b1[k], 0.0f);
    }
    float acc = 0.0f;
    #pragma unroll
    for (int k = 0; k < HIDDEN; k++) {
        const float v = __shfl_sync(0xffffffff, r[k >> 5], k & 31);
        acc = fmaf(v, W2[k * N_CLS + lane], acc);
    }
    g_h2[(size_t)node * N_CLS + lane] = acc;
}

// Layer-2 aggregation: 32 threads per (edge | self-loop), one scalar atomic each
__global__ void k_scatter2(const int* __restrict__ src,
                           const int* __restrict__ dst,
                           float* __restrict__ out, int E) {
    const int warp = (blockIdx.x * blockDim.x + threadIdx.x) >> 5;
    const int lane = threadIdx.x & 31;
    if (warp >= E + N_NODES) return;
    int s, d; float norm;
    if (warp < E) {
        s = src[warp];
        d = dst[warp];
        norm = g_deg[s] * g_deg[d];
    } else {
        s = d = warp - E;
        const float v = g_deg[s];
        norm = v * v;
    }
    const float v = g_h2[(size_t)s * N_CLS + lane];
    atomicAdd(out + (size_t)d * N_CLS + lane, v * norm);
}

// out = log_softmax(out + b2)  (warp per node, 32 classes == 32 lanes)
__global__ void k_lsm(float* __restrict__ out, const float* __restrict__ b2) {
    const int node = (blockIdx.x * blockDim.x + threadIdx.x) >> 5;
    const int lane = threadIdx.x & 31;
    if (node >= N_NODES) return;
    float v = out[(size_t)node * N_CLS + lane] + b2[lane];
    float m = v;
    #pragma unroll
    for (int o = 16; o > 0; o >>= 1)
        m = fmaxf(m, __shfl_xor_sync(0xffffffff, m, o));
    float s = expf(v - m);
    #pragma unroll
    for (int o = 16; o > 0; o >>= 1)
        s += __shfl_xor_sync(0xffffffff, s, o);
    out[(size_t)node * N_CLS + lane] = v - m - logf(s);
}

// ---------------- launcher ----------------
extern "C" void kernel_launch(void* const* d_in, const int* in_sizes, int n_in,
                              void* d_out, int out_size) {
    const float* x  = (const float*)d_in[0];
    const int*   ei = (const int*)d_in[1];    // int32! (jax x64 disabled)
    const float* W1 = (const float*)d_in[2];
    const float* b1 = (const float*)d_in[3];
    const float* W2 = (const float*)d_in[4];
    const float* b2 = (const float*)d_in[5];
    float* out = (float*)d_out;

    const int E = in_sizes[1] / 2;            // 3.2M int32 elements -> 1.6M edges
    const int* src = ei;
    const int* dst = ei + E;

    k_init<<<2048, 256>>>(out);
    k_deg<<<(E + 255) / 256, 256>>>(dst, E);
    k_dinv<<<(N_NODES + 255) / 256, 256>>>();
    k_gemm1<<<(N_NODES + BM - 1) / BM, 256>>>(x, W1);
    {
        const long long work = (long long)(E + N_NODES) * 32;
        k_scatter1<<<(unsigned)((work + 255) / 256), 256>>>(src, dst, E);
    }
    k_gemm2<<<(N_NODES * 32 + 255) / 256, 256>>>(b1, W2);
    {
        const long long work = (long long)(E + N_NODES) * 32;
        k_scatter2<<<(unsigned)((work + 255) / 256), 256>>>(src, dst, out, E);
    }
    k_lsm<<<(N_NODES * 32 + 255) / 256, 256>>>(out, b2);
}

// round 6
// speedup vs baseline: 1.8150x; 1.8150x over previous
#include <cuda_runtime.h>
#include <cuda_bf16.h>
#include <math.h>

#define N_NODES  50000
#define N_EDGES  1600000
#define D_FEAT   512
#define HIDDEN   128
#define N_CLS    32

// ---------------- device scratch (no allocs allowed) ----------------
__device__ __align__(256) int   g_cnt   [N_NODES];        // in-degree, then cursor
__device__ __align__(256) int   g_rowptr[N_NODES + 1];
__device__ __align__(256) float g_dinv  [N_NODES];
__device__ __align__(256) int   g_srcs  [N_EDGES];        // CSR: src per slot (sorted by dst)
__device__ __align__(256) float g_w     [N_EDGES];        // dinv[src] per slot
__device__ __align__(256) float g_h1  [(size_t)N_NODES * HIDDEN]; // x @ W1
__device__ __align__(256) float g_agg1[(size_t)N_NODES * HIDDEN]; // relu(A_hat h1 + b1)
__device__ __align__(256) float g_h2  [(size_t)N_NODES * N_CLS];  // agg1 @ W2

// ---------------- CSR build ----------------

__global__ void k_zero_cnt() {
    int i = blockIdx.x * blockDim.x + threadIdx.x;
    if (i < N_NODES) g_cnt[i] = 0;
}

// in-degree histogram (int atomics, spread addresses)
__global__ void k_count(const int* __restrict__ dst, int E) {
    int e = blockIdx.x * blockDim.x + threadIdx.x;
    if (e < E) atomicAdd(&g_cnt[dst[e]], 1);
}

// single-block exclusive scan of g_cnt -> g_rowptr; also dinv = rsqrt(cnt+1); cnt -> 0
__global__ __launch_bounds__(1024) void k_scan() {
    __shared__ int sums[1024];
    const int t = threadIdx.x;
    const int CH = (N_NODES + 1023) / 1024;   // 49
    const int base = t * CH;
    int local = 0;
    for (int i = 0; i < CH; i++) {
        int idx = base + i;
        if (idx < N_NODES) local += g_cnt[idx];
    }
    sums[t] = local;
    __syncthreads();
    // Hillis-Steele inclusive scan over 1024 partials
    for (int off = 1; off < 1024; off <<= 1) {
        int v = (t >= off) ? sums[t - off] : 0;
        __syncthreads();
        sums[t] += v;
        __syncthreads();
    }
    int run = (t == 0) ? 0 : sums[t - 1];
    for (int i = 0; i < CH; i++) {
        int idx = base + i;
        if (idx < N_NODES) {
            int c = g_cnt[idx];
            g_rowptr[idx] = run;
            run += c;
            g_dinv[idx] = rsqrtf((float)(c + 1));   // +1 self-loop
            g_cnt[idx] = 0;                          // reuse as cursor
        }
    }
    if (t == 1023) g_rowptr[N_NODES] = run;
}

// scatter edge (src, dinv[src]) into dst-sorted slots
__global__ void k_fill(const int* __restrict__ src, const int* __restrict__ dst, int E) {
    int e = blockIdx.x * blockDim.x + threadIdx.x;
    if (e >= E) return;
    int d = dst[e], s = src[e];
    int pos = g_rowptr[d] + atomicAdd(&g_cnt[d], 1);
    g_srcs[pos] = s;
    g_w[pos] = g_dinv[s];
}

// ---------------- h1 = x @ W1  (fp32 tiled SGEMM 128x128x8) ----------------
#define BM 128
#define BK 8
__global__ __launch_bounds__(256) void k_gemm1(const float* __restrict__ A,
                                               const float* __restrict__ B) {
    __shared__ float As[BK][BM];
    __shared__ float Bs[BK][BM];
    const int tid = threadIdx.x;
    const int row0 = blockIdx.x * BM;
    const int tx = tid % 16;
    const int ty = tid / 16;
    const int arow = tid >> 1, acol = (tid & 1) * 4;
    const int brow = tid >> 5, bcol = (tid & 31) * 4;

    float acc[8][8];
    #pragma unroll
    for (int i = 0; i < 8; i++)
        #pragma unroll
        for (int j = 0; j < 8; j++) acc[i][j] = 0.0f;

    for (int k0 = 0; k0 < D_FEAT; k0 += BK) {
        float4 a = make_float4(0.f, 0.f, 0.f, 0.f);
        const int gr = row0 + arow;
        if (gr < N_NODES)
            a = *(const float4*)(A + (size_t)gr * D_FEAT + k0 + acol);
        As[acol + 0][arow] = a.x;
        As[acol + 1][arow] = a.y;
        As[acol + 2][arow] = a.z;
        As[acol + 3][arow] = a.w;

        float4 b = *(const float4*)(B + (size_t)(k0 + brow) * HIDDEN + bcol);
        Bs[brow][bcol + 0] = b.x;
        Bs[brow][bcol + 1] = b.y;
        Bs[brow][bcol + 2] = b.z;
        Bs[brow][bcol + 3] = b.w;
        __syncthreads();

        #pragma unroll
        for (int k = 0; k < BK; k++) {
            float ra[8], rb[8];
            #pragma unroll
            for (int i = 0; i < 8; i++) ra[i] = As[k][ty * 8 + i];
            #pragma unroll
            for (int j = 0; j < 8; j++) rb[j] = Bs[k][tx * 8 + j];
            #pragma unroll
            for (int i = 0; i < 8; i++)
                #pragma unroll
                for (int j = 0; j < 8; j++)
                    acc[i][j] = fmaf(ra[i], rb[j], acc[i][j]);
        }
        __syncthreads();
    }

    #pragma unroll
    for (int i = 0; i < 8; i++) {
        const int gr = row0 + ty * 8 + i;
        if (gr < N_NODES) {
            float4* cp = (float4*)(g_h1 + (size_t)gr * HIDDEN + tx * 8);
            cp[0] = make_float4(acc[i][0], acc[i][1], acc[i][2], acc[i][3]);
            cp[1] = make_float4(acc[i][4], acc[i][5], acc[i][6], acc[i][7]);
        }
    }
}

// ---------------- layer-1 aggregation: pull gather, warp per node ----------------
// agg1[d] = relu( dinv[d]*(sum_in dinv[s]*h1[s] + dinv[d]*h1[d]) + b1 )
__global__ void k_gather1(const float* __restrict__ b1) {
    const int node = (blockIdx.x * blockDim.x + threadIdx.x) >> 5;
    const int lane = threadIdx.x & 31;
    if (node >= N_NODES) return;
    const int beg = g_rowptr[node];
    const int end = g_rowptr[node + 1];

    float4 acc = make_float4(0.f, 0.f, 0.f, 0.f);
    int i = beg;
    // unroll by 2 for MLP
    for (; i + 1 < end; i += 2) {
        const int   s0 = g_srcs[i],   s1 = g_srcs[i + 1];
        const float w0 = g_w[i],      w1 = g_w[i + 1];
        const float4 v0 = *(const float4*)(g_h1 + (size_t)s0 * HIDDEN + lane * 4);
        const float4 v1 = *(const float4*)(g_h1 + (size_t)s1 * HIDDEN + lane * 4);
        acc.x = fmaf(w0, v0.x, acc.x); acc.y = fmaf(w0, v0.y, acc.y);
        acc.z = fmaf(w0, v0.z, acc.z); acc.w = fmaf(w0, v0.w, acc.w);
        acc.x = fmaf(w1, v1.x, acc.x); acc.y = fmaf(w1, v1.y, acc.y);
        acc.z = fmaf(w1, v1.z, acc.z); acc.w = fmaf(w1, v1.w, acc.w);
    }
    if (i < end) {
        const int   s0 = g_srcs[i];
        const float w0 = g_w[i];
        const float4 v0 = *(const float4*)(g_h1 + (size_t)s0 * HIDDEN + lane * 4);
        acc.x = fmaf(w0, v0.x, acc.x); acc.y = fmaf(w0, v0.y, acc.y);
        acc.z = fmaf(w0, v0.z, acc.z); acc.w = fmaf(w0, v0.w, acc.w);
    }

    const float di = g_dinv[node];
    const float4 self = *(const float4*)(g_h1 + (size_t)node * HIDDEN + lane * 4);
    acc.x = fmaf(di, self.x, acc.x); acc.y = fmaf(di, self.y, acc.y);
    acc.z = fmaf(di, self.z, acc.z); acc.w = fmaf(di, self.w, acc.w);

    const float4 bb = *(const float4*)(b1 + lane * 4);
    float4 r;
    r.x = fmaxf(fmaf(di, acc.x, bb.x), 0.f);
    r.y = fmaxf(fmaf(di, acc.y, bb.y), 0.f);
    r.z = fmaxf(fmaf(di, acc.z, bb.z), 0.f);
    r.w = fmaxf(fmaf(di, acc.w, bb.w), 0.f);
    *(float4*)(g_agg1 + (size_t)node * HIDDEN + lane * 4) = r;
}

// ---------------- h2 = agg1 @ W2  (warp per node) ----------------
__global__ void k_gemm2(const float* __restrict__ W2) {
    const int node = (blockIdx.x * blockDim.x + threadIdx.x) >> 5;
    const int lane = threadIdx.x & 31;
    if (node >= N_NODES) return;
    float r[4];
    #pragma unroll
    for (int c = 0; c < 4; c++)
        r[c] = g_agg1[(size_t)node * HIDDEN + c * 32 + lane];
    float acc = 0.0f;
    #pragma unroll
    for (int k = 0; k < HIDDEN; k++) {
        const float v = __shfl_sync(0xffffffff, r[k >> 5], k & 31);
        acc = fmaf(v, W2[k * N_CLS + lane], acc);
    }
    g_h2[(size_t)node * N_CLS + lane] = acc;
}

// ---------------- layer-2 aggregation + bias + log-softmax, warp per node ----------------
__global__ void k_gather2(float* __restrict__ out, const float* __restrict__ b2) {
    const int node = (blockIdx.x * blockDim.x + threadIdx.x) >> 5;
    const int lane = threadIdx.x & 31;
    if (node >= N_NODES) return;
    const int beg = g_rowptr[node];
    const int end = g_rowptr[node + 1];

    float acc = 0.f;
    int i = beg;
    for (; i + 1 < end; i += 2) {
        const int   s0 = g_srcs[i],   s1 = g_srcs[i + 1];
        const float w0 = g_w[i],      w1 = g_w[i + 1];
        const float v0 = g_h2[(size_t)s0 * N_CLS + lane];
        const float v1 = g_h2[(size_t)s1 * N_CLS + lane];
        acc = fmaf(w0, v0, acc);
        acc = fmaf(w1, v1, acc);
    }
    if (i < end)
        acc = fmaf(g_w[i], g_h2[(size_t)g_srcs[i] * N_CLS + lane], acc);

    const float di = g_dinv[node];
    acc = fmaf(di, g_h2[(size_t)node * N_CLS + lane], acc);
    float v = fmaf(di, acc, b2[lane]);

    // log-softmax across the warp (32 classes == 32 lanes)
    float m = v;
    #pragma unroll
    for (int o = 16; o > 0; o >>= 1)
        m = fmaxf(m, __shfl_xor_sync(0xffffffff, m, o));
    float s = expf(v - m);
    #pragma unroll
    for (int o = 16; o > 0; o >>= 1)
        s += __shfl_xor_sync(0xffffffff, s, o);
    out[(size_t)node * N_CLS + lane] = v - m - logf(s);
}

// ---------------- launcher ----------------
extern "C" void kernel_launch(void* const* d_in, const int* in_sizes, int n_in,
                              void* d_out, int out_size) {
    const float* x  = (const float*)d_in[0];
    const int*   ei = (const int*)d_in[1];    // int32 (jax x64 disabled)
    const float* W1 = (const float*)d_in[2];
    const float* b1 = (const float*)d_in[3];
    const float* W2 = (const float*)d_in[4];
    const float* b2 = (const float*)d_in[5];
    float* out = (float*)d_out;

    const int E = in_sizes[1] / 2;
    const int* src = ei;
    const int* dst = ei + E;

    k_zero_cnt<<<(N_NODES + 255) / 256, 256>>>();
    k_count<<<(E + 255) / 256, 256>>>(dst, E);
    k_scan<<<1, 1024>>>();
    k_fill<<<(E + 255) / 256, 256>>>(src, dst, E);
    k_gemm1<<<(N_NODES + BM - 1) / BM, 256>>>(x, W1);
    k_gather1<<<(N_NODES * 32 + 255) / 256, 256>>>(b1);
    k_gemm2<<<(N_NODES * 32 + 255) / 256, 256>>>(W2);
    k_gather2<<<(N_NODES * 32 + 255) / 256, 256>>>(out, b2);
}

// round 8
// speedup vs baseline: 2.5164x; 1.3865x over previous
#include <cuda_runtime.h>
#include <cuda_bf16.h>
#include <math.h>

#define N_NODES  50000
#define N_EDGES  1600000
#define D_FEAT   512
#define HIDDEN   128
#define N_CLS    32

// ---------------- device scratch (no allocs allowed) ----------------
__device__ __align__(256) int   g_cnt   [N_NODES];        // in-degree, then cursor
__device__ __align__(256) int   g_rowptr[N_NODES + 1];
__device__ __align__(256) float g_dinv  [N_NODES];
__device__ __align__(256) int   g_srcs  [N_EDGES];        // CSR: src per slot (sorted by dst)
__device__ __align__(256) float g_w     [N_EDGES];        // dinv[src] per slot
__device__ __align__(256) float g_h1  [(size_t)N_NODES * HIDDEN]; // x @ W1
__device__ __align__(256) float g_agg1[(size_t)N_NODES * HIDDEN]; // relu(A_hat h1 + b1)
__device__ __align__(256) float g_h2  [(size_t)N_NODES * N_CLS];  // agg1 @ W2

// ---------------- CSR build ----------------

__global__ void k_zero_cnt() {
    int i = blockIdx.x * blockDim.x + threadIdx.x;
    if (i < N_NODES) g_cnt[i] = 0;
}

__global__ void k_count(const int* __restrict__ dst, int E) {
    int e = blockIdx.x * blockDim.x + threadIdx.x;
    if (e < E) atomicAdd(&g_cnt[dst[e]], 1);
}

__global__ __launch_bounds__(1024) void k_scan() {
    __shared__ int sums[1024];
    const int t = threadIdx.x;
    const int CH = (N_NODES + 1023) / 1024;
    const int base = t * CH;
    int local = 0;
    for (int i = 0; i < CH; i++) {
        int idx = base + i;
        if (idx < N_NODES) local += g_cnt[idx];
    }
    sums[t] = local;
    __syncthreads();
    for (int off = 1; off < 1024; off <<= 1) {
        int v = (t >= off) ? sums[t - off] : 0;
        __syncthreads();
        sums[t] += v;
        __syncthreads();
    }
    int run = (t == 0) ? 0 : sums[t - 1];
    for (int i = 0; i < CH; i++) {
        int idx = base + i;
        if (idx < N_NODES) {
            int c = g_cnt[idx];
            g_rowptr[idx] = run;
            run += c;
            g_dinv[idx] = rsqrtf((float)(c + 1));
            g_cnt[idx] = 0;
        }
    }
    if (t == 1023) g_rowptr[N_NODES] = run;
}

__global__ void k_fill(const int* __restrict__ src, const int* __restrict__ dst, int E) {
    int e = blockIdx.x * blockDim.x + threadIdx.x;
    if (e >= E) return;
    int d = dst[e], s = src[e];
    int pos = g_rowptr[d] + atomicAdd(&g_cnt[d], 1);
    g_srcs[pos] = s;
    g_w[pos] = g_dinv[s];
}

// ---------------- h1 = x @ W1 via tf32 mma.sync (m16n8k8) ----------------
// Block 128x128, K staged 16 wide, double-buffered smem.
// 8 warps in 4x2: warp tile 32x64 = 2 (m) x 8 (n) mma tiles.
#define PK 20    // A smem row pitch (16 + 4 pad) -> conflict-free frag loads
#define PN 136   // B smem row pitch (128 + 8 pad) -> conflict-free frag loads

__device__ __forceinline__ unsigned f2tf32(float f) {
    unsigned r;
    asm("cvt.rna.tf32.f32 %0, %1;" : "=r"(r) : "f"(f));
    return r;
}

__global__ __launch_bounds__(256) void k_gemm1_tc(const float* __restrict__ A,
                                                  const float* __restrict__ B) {
    __shared__ unsigned As[2][128 * PK];
    __shared__ unsigned Bs[2][16 * PN];

    const int tid  = threadIdx.x;
    const int lane = tid & 31;
    const int warp = tid >> 5;
    const int wm = warp >> 1;          // 0..3
    const int wn = warp & 1;           // 0..1
    const int row0 = blockIdx.x * 128;

    float c[2][8][4];
    #pragma unroll
    for (int mt = 0; mt < 2; mt++)
        #pragma unroll
        for (int nt = 0; nt < 8; nt++)
            #pragma unroll
            for (int q = 0; q < 4; q++) c[mt][nt][q] = 0.0f;

    // stage-load helpers (each thread: 2 float4 of A, 2 float4 of B)
    const int af0 = tid, af1 = tid + 256;         // f -> r = f>>2, c4 = f&3
    const int bf0 = tid, bf1 = tid + 256;         // f -> k = f>>5, n4 = f&31

    auto ldA = [&](int k0, float4& p0, float4& p1) {
        int r0 = af0 >> 2, c40 = af0 & 3;
        int r1 = af1 >> 2, c41 = af1 & 3;
        int gr0 = row0 + r0, gr1 = row0 + r1;
        p0 = (gr0 < N_NODES) ? *(const float4*)(A + (size_t)gr0 * D_FEAT + k0 + c40 * 4)
                             : make_float4(0.f, 0.f, 0.f, 0.f);
        p1 = (gr1 < N_NODES) ? *(const float4*)(A + (size_t)gr1 * D_FEAT + k0 + c41 * 4)
                             : make_float4(0.f, 0.f, 0.f, 0.f);
    };
    auto ldB = [&](int k0, float4& p0, float4& p1) {
        int k_0 = bf0 >> 5, n40 = bf0 & 31;
        int k_1 = bf1 >> 5, n41 = bf1 & 31;
        p0 = *(const float4*)(B + (size_t)(k0 + k_0) * HIDDEN + n40 * 4);
        p1 = *(const float4*)(B + (size_t)(k0 + k_1) * HIDDEN + n41 * 4);
    };
    auto stA = [&](int buf, const float4& p0, const float4& p1) {
        int r0 = af0 >> 2, c40 = af0 & 3;
        int r1 = af1 >> 2, c41 = af1 & 3;
        unsigned* a0 = &As[buf][r0 * PK + c40 * 4];
        a0[0] = f2tf32(p0.x); a0[1] = f2tf32(p0.y); a0[2] = f2tf32(p0.z); a0[3] = f2tf32(p0.w);
        unsigned* a1 = &As[buf][r1 * PK + c41 * 4];
        a1[0] = f2tf32(p1.x); a1[1] = f2tf32(p1.y); a1[2] = f2tf32(p1.z); a1[3] = f2tf32(p1.w);
    };
    auto stB = [&](int buf, const float4& p0, const float4& p1) {
        int k_0 = bf0 >> 5, n40 = bf0 & 31;
        int k_1 = bf1 >> 5, n41 = bf1 & 31;
        unsigned* b0 = &Bs[buf][k_0 * PN + n40 * 4];
        b0[0] = f2tf32(p0.x); b0[1] = f2tf32(p0.y); b0[2] = f2tf32(p0.z); b0[3] = f2tf32(p0.w);
        unsigned* b1 = &Bs[buf][k_1 * PN + n41 * 4];
        b1[0] = f2tf32(p1.x); b1[1] = f2tf32(p1.y); b1[2] = f2tf32(p1.z); b1[3] = f2tf32(p1.w);
    };

    // prologue: stage 0
    {
        float4 a0, a1, b0, b1;
        ldA(0, a0, a1);
        ldB(0, b0, b1);
        stA(0, a0, a1);
        stB(0, b0, b1);
    }
    __syncthreads();

    const int NSTAGE = D_FEAT / 16;   // 32
    const int rA = lane >> 2;         // 0..7
    const int cA = lane & 3;          // 0..3

    for (int s = 0; s < NSTAGE; s++) {
        const int cur = s & 1;
        float4 pa0, pa1, pb0, pb1;
        if (s + 1 < NSTAGE) {
            ldA((s + 1) * 16, pa0, pa1);
            ldB((s + 1) * 16, pb0, pb1);
        }

        #pragma unroll
        for (int ks = 0; ks < 2; ks++) {
            const int kk = ks * 8;
            unsigned afr[2][4];
            #pragma unroll
            for (int mt = 0; mt < 2; mt++) {
                const int r = wm * 32 + mt * 16 + rA;
                afr[mt][0] = As[cur][r * PK + kk + cA];
                afr[mt][1] = As[cur][(r + 8) * PK + kk + cA];
                afr[mt][2] = As[cur][r * PK + kk + cA + 4];
                afr[mt][3] = As[cur][(r + 8) * PK + kk + cA + 4];
            }
            #pragma unroll
            for (int nt = 0; nt < 8; nt++) {
                const int n = wn * 64 + nt * 8 + rA;
                const unsigned bfr0 = Bs[cur][(kk + cA) * PN + n];
                const unsigned bfr1 = Bs[cur][(kk + 4 + cA) * PN + n];
                #pragma unroll
                for (int mt = 0; mt < 2; mt++) {
                    asm volatile(
                        "mma.sync.aligned.m16n8k8.row.col.f32.tf32.tf32.f32 "
                        "{%0,%1,%2,%3}, {%4,%5,%6,%7}, {%8,%9}, {%0,%1,%2,%3};"
                        : "+f"(c[mt][nt][0]), "+f"(c[mt][nt][1]),
                          "+f"(c[mt][nt][2]), "+f"(c[mt][nt][3])
                        : "r"(afr[mt][0]), "r"(afr[mt][1]),
                          "r"(afr[mt][2]), "r"(afr[mt][3]),
                          "r"(bfr0), "r"(bfr1));
                }
            }
        }

        if (s + 1 < NSTAGE) {
            stA(cur ^ 1, pa0, pa1);
            stB(cur ^ 1, pb0, pb1);
            __syncthreads();
        }
    }

    // epilogue: c[mt][nt] -> g_h1
    #pragma unroll
    for (int mt = 0; mt < 2; mt++) {
        const int r_lo = row0 + wm * 32 + mt * 16 + rA;
        const int r_hi = r_lo + 8;
        #pragma unroll
        for (int nt = 0; nt < 8; nt++) {
            const int col = wn * 64 + nt * 8 + 2 * cA;
            if (r_lo < N_NODES)
                *(float2*)(g_h1 + (size_t)r_lo * HIDDEN + col) =
                    make_float2(c[mt][nt][0], c[mt][nt][1]);
            if (r_hi < N_NODES)
                *(float2*)(g_h1 + (size_t)r_hi * HIDDEN + col) =
                    make_float2(c[mt][nt][2], c[mt][nt][3]);
        }
    }
}

// ---------------- layer-1 aggregation: pull gather, warp per node ----------------
__global__ void k_gather1(const float* __restrict__ b1) {
    const int node = (blockIdx.x * blockDim.x + threadIdx.x) >> 5;
    const int lane = threadIdx.x & 31;
    if (node >= N_NODES) return;
    const int beg = g_rowptr[node];
    const int end = g_rowptr[node + 1];

    float4 acc = make_float4(0.f, 0.f, 0.f, 0.f);
    int i = beg;
    for (; i + 1 < end; i += 2) {
        const int   s0 = g_srcs[i],   s1 = g_srcs[i + 1];
        const float w0 = g_w[i],      w1 = g_w[i + 1];
        const float4 v0 = *(const float4*)(g_h1 + (size_t)s0 * HIDDEN + lane * 4);
        const float4 v1 = *(const float4*)(g_h1 + (size_t)s1 * HIDDEN + lane * 4);
        acc.x = fmaf(w0, v0.x, acc.x); acc.y = fmaf(w0, v0.y, acc.y);
        acc.z = fmaf(w0, v0.z, acc.z); acc.w = fmaf(w0, v0.w, acc.w);
        acc.x = fmaf(w1, v1.x, acc.x); acc.y = fmaf(w1, v1.y, acc.y);
        acc.z = fmaf(w1, v1.z, acc.z); acc.w = fmaf(w1, v1.w, acc.w);
    }
    if (i < end) {
        const int   s0 = g_srcs[i];
        const float w0 = g_w[i];
        const float4 v0 = *(const float4*)(g_h1 + (size_t)s0 * HIDDEN + lane * 4);
        acc.x = fmaf(w0, v0.x, acc.x); acc.y = fmaf(w0, v0.y, acc.y);
        acc.z = fmaf(w0, v0.z, acc.z); acc.w = fmaf(w0, v0.w, acc.w);
    }

    const float di = g_dinv[node];
    const float4 self = *(const float4*)(g_h1 + (size_t)node * HIDDEN + lane * 4);
    acc.x = fmaf(di, self.x, acc.x); acc.y = fmaf(di, self.y, acc.y);
    acc.z = fmaf(di, self.z, acc.z); acc.w = fmaf(di, self.w, acc.w);

    const float4 bb = *(const float4*)(b1 + lane * 4);
    float4 r;
    r.x = fmaxf(fmaf(di, acc.x, bb.x), 0.f);
    r.y = fmaxf(fmaf(di, acc.y, bb.y), 0.f);
    r.z = fmaxf(fmaf(di, acc.z, bb.z), 0.f);
    r.w = fmaxf(fmaf(di, acc.w, bb.w), 0.f);
    *(float4*)(g_agg1 + (size_t)node * HIDDEN + lane * 4) = r;
}

// ---------------- h2 = agg1 @ W2  (warp per node) ----------------
__global__ void k_gemm2(const float* __restrict__ W2) {
    const int node = (blockIdx.x * blockDim.x + threadIdx.x) >> 5;
    const int lane = threadIdx.x & 31;
    if (node >= N_NODES) return;
    float r[4];
    #pragma unroll
    for (int c = 0; c < 4; c++)
        r[c] = g_agg1[(size_t)node * HIDDEN + c * 32 + lane];
    float acc = 0.0f;
    #pragma unroll
    for (int k = 0; k < HIDDEN; k++) {
        const float v = __shfl_sync(0xffffffff, r[k >> 5], k & 31);
        acc = fmaf(v, W2[k * N_CLS + lane], acc);
    }
    g_h2[(size_t)node * N_CLS + lane] = acc;
}

// ---------------- layer-2 aggregation + bias + log-softmax ----------------
__global__ void k_gather2(float* __restrict__ out, const float* __restrict__ b2) {
    const int node = (blockIdx.x * blockDim.x + threadIdx.x) >> 5;
    const int lane = threadIdx.x & 31;
    if (node >= N_NODES) return;
    const int beg = g_rowptr[node];
    const int end = g_rowptr[node + 1];

    float acc = 0.f;
    int i = beg;
    for (; i + 1 < end; i += 2) {
        const int   s0 = g_srcs[i],   s1 = g_srcs[i + 1];
        const float w0 = g_w[i],      w1 = g_w[i + 1];
        const float v0 = g_h2[(size_t)s0 * N_CLS + lane];
        const float v1 = g_h2[(size_t)s1 * N_CLS + lane];
        acc = fmaf(w0, v0, acc);
        acc = fmaf(w1, v1, acc);
    }
    if (i < end)
        acc = fmaf(g_w[i], g_h2[(size_t)g_srcs[i] * N_CLS + lane], acc);

    const float di = g_dinv[node];
    acc = fmaf(di, g_h2[(size_t)node * N_CLS + lane], acc);
    float v = fmaf(di, acc, b2[lane]);

    float m = v;
    #pragma unroll
    for (int o = 16; o > 0; o >>= 1)
        m = fmaxf(m, __shfl_xor_sync(0xffffffff, m, o));
    float s = expf(v - m);
    #pragma unroll
    for (int o = 16; o > 0; o >>= 1)
        s += __shfl_xor_sync(0xffffffff, s, o);
    out[(size_t)node * N_CLS + lane] = v - m - logf(s);
}

// ---------------- launcher ----------------
extern "C" void kernel_launch(void* const* d_in, const int* in_sizes, int n_in,
                              void* d_out, int out_size) {
    const float* x  = (const float*)d_in[0];
    const int*   ei = (const int*)d_in[1];    // int32 (jax x64 disabled)
    const float* W1 = (const float*)d_in[2];
    const float* b1 = (const float*)d_in[3];
    const float* W2 = (const float*)d_in[4];
    const float* b2 = (const float*)d_in[5];
    float* out = (float*)d_out;

    const int E = in_sizes[1] / 2;
    const int* src = ei;
    const int* dst = ei + E;

    k_zero_cnt<<<(N_NODES + 255) / 256, 256>>>();
    k_count<<<(E + 255) / 256, 256>>>(dst, E);
    k_scan<<<1, 1024>>>();
    k_fill<<<(E + 255) / 256, 256>>>(src, dst, E);
    k_gemm1_tc<<<(N_NODES + 127) / 128, 256>>>(x, W1);
    k_gather1<<<(N_NODES * 32 + 255) / 256, 256>>>(b1);
    k_gemm2<<<(N_NODES * 32 + 255) / 256, 256>>>(W2);
    k_gather2<<<(N_NODES * 32 + 255) / 256, 256>>>(out, b2);
}

// round 9
// speedup vs baseline: 2.6149x; 1.0391x over previous
#include <cuda_runtime.h>
#include <cuda_bf16.h>
#include <math.h>

#define N_NODES  50000
#define N_EDGES  1600000
#define D_FEAT   512
#define HIDDEN   128
#define N_CLS    32

// ---------------- device scratch (no allocs allowed) ----------------
__device__ __align__(256) int   g_cnt   [N_NODES];        // in-degree, then cursor
__device__ __align__(256) int   g_rowptr[N_NODES + 1];
__device__ __align__(256) float g_dinv  [N_NODES];
__device__ __align__(256) int   g_srcs  [N_EDGES];        // CSR: src per slot (sorted by dst)
__device__ __align__(256) __nv_bfloat162 g_h1b[(size_t)N_NODES * (HIDDEN / 2)]; // x@W1, bf16
__device__ __align__(256) float g_agg1[(size_t)N_NODES * HIDDEN]; // relu(A_hat h1 + b1)
__device__ __align__(256) float g_h2  [(size_t)N_NODES * N_CLS];  // agg1 @ W2

// ---------------- CSR build ----------------

__global__ void k_zero_cnt() {
    int i = blockIdx.x * blockDim.x + threadIdx.x;
    if (i < N_NODES) g_cnt[i] = 0;
}

__global__ void k_count(const int* __restrict__ dst, int E) {
    int e = blockIdx.x * blockDim.x + threadIdx.x;
    if (e < E) atomicAdd(&g_cnt[dst[e]], 1);
}

__global__ __launch_bounds__(1024) void k_scan() {
    __shared__ int sums[1024];
    const int t = threadIdx.x;
    const int CH = (N_NODES + 1023) / 1024;
    const int base = t * CH;
    int local = 0;
    for (int i = 0; i < CH; i++) {
        int idx = base + i;
        if (idx < N_NODES) local += g_cnt[idx];
    }
    sums[t] = local;
    __syncthreads();
    for (int off = 1; off < 1024; off <<= 1) {
        int v = (t >= off) ? sums[t - off] : 0;
        __syncthreads();
        sums[t] += v;
        __syncthreads();
    }
    int run = (t == 0) ? 0 : sums[t - 1];
    for (int i = 0; i < CH; i++) {
        int idx = base + i;
        if (idx < N_NODES) {
            int c = g_cnt[idx];
            g_rowptr[idx] = run;
            run += c;
            g_dinv[idx] = rsqrtf((float)(c + 1));
            g_cnt[idx] = 0;
        }
    }
    if (t == 1023) g_rowptr[N_NODES] = run;
}

__global__ void k_fill(const int* __restrict__ src, const int* __restrict__ dst, int E) {
    int e = blockIdx.x * blockDim.x + threadIdx.x;
    if (e >= E) return;
    int d = dst[e];
    int pos = g_rowptr[d] + atomicAdd(&g_cnt[d], 1);
    g_srcs[pos] = src[e];
}

// ---------------- h1 = x @ W1 via tf32 mma.sync (m16n8k8), bf16 output ----------------
#define PK 20    // A smem row pitch (16 + 4 pad)
#define PN 136   // B smem row pitch (128 + 8 pad)

__device__ __forceinline__ unsigned f2tf32(float f) {
    unsigned r;
    asm("cvt.rna.tf32.f32 %0, %1;" : "=r"(r) : "f"(f));
    return r;
}

__global__ __launch_bounds__(256) void k_gemm1_tc(const float* __restrict__ A,
                                                  const float* __restrict__ B) {
    __shared__ unsigned As[2][128 * PK];
    __shared__ unsigned Bs[2][16 * PN];

    const int tid  = threadIdx.x;
    const int lane = tid & 31;
    const int warp = tid >> 5;
    const int wm = warp >> 1;
    const int wn = warp & 1;
    const int row0 = blockIdx.x * 128;

    float c[2][8][4];
    #pragma unroll
    for (int mt = 0; mt < 2; mt++)
        #pragma unroll
        for (int nt = 0; nt < 8; nt++)
            #pragma unroll
            for (int q = 0; q < 4; q++) c[mt][nt][q] = 0.0f;

    const int af0 = tid, af1 = tid + 256;
    const int bf0 = tid, bf1 = tid + 256;

    auto ldA = [&](int k0, float4& p0, float4& p1) {
        int r0 = af0 >> 2, c40 = af0 & 3;
        int r1 = af1 >> 2, c41 = af1 & 3;
        int gr0 = row0 + r0, gr1 = row0 + r1;
        p0 = (gr0 < N_NODES) ? *(const float4*)(A + (size_t)gr0 * D_FEAT + k0 + c40 * 4)
                             : make_float4(0.f, 0.f, 0.f, 0.f);
        p1 = (gr1 < N_NODES) ? *(const float4*)(A + (size_t)gr1 * D_FEAT + k0 + c41 * 4)
                             : make_float4(0.f, 0.f, 0.f, 0.f);
    };
    auto ldB = [&](int k0, float4& p0, float4& p1) {
        int k_0 = bf0 >> 5, n40 = bf0 & 31;
        int k_1 = bf1 >> 5, n41 = bf1 & 31;
        p0 = *(const float4*)(B + (size_t)(k0 + k_0) * HIDDEN + n40 * 4);
        p1 = *(const float4*)(B + (size_t)(k0 + k_1) * HIDDEN + n41 * 4);
    };
    auto stA = [&](int buf, const float4& p0, const float4& p1) {
        int r0 = af0 >> 2, c40 = af0 & 3;
        int r1 = af1 >> 2, c41 = af1 & 3;
        unsigned* a0 = &As[buf][r0 * PK + c40 * 4];
        a0[0] = f2tf32(p0.x); a0[1] = f2tf32(p0.y); a0[2] = f2tf32(p0.z); a0[3] = f2tf32(p0.w);
        unsigned* a1 = &As[buf][r1 * PK + c41 * 4];
        a1[0] = f2tf32(p1.x); a1[1] = f2tf32(p1.y); a1[2] = f2tf32(p1.z); a1[3] = f2tf32(p1.w);
    };
    auto stB = [&](int buf, const float4& p0, const float4& p1) {
        int k_0 = bf0 >> 5, n40 = bf0 & 31;
        int k_1 = bf1 >> 5, n41 = bf1 & 31;
        unsigned* b0 = &Bs[buf][k_0 * PN + n40 * 4];
        b0[0] = f2tf32(p0.x); b0[1] = f2tf32(p0.y); b0[2] = f2tf32(p0.z); b0[3] = f2tf32(p0.w);
        unsigned* b1 = &Bs[buf][k_1 * PN + n41 * 4];
        b1[0] = f2tf32(p1.x); b1[1] = f2tf32(p1.y); b1[2] = f2tf32(p1.z); b1[3] = f2tf32(p1.w);
    };

    {
        float4 a0, a1, b0, b1;
        ldA(0, a0, a1);
        ldB(0, b0, b1);
        stA(0, a0, a1);
        stB(0, b0, b1);
    }
    __syncthreads();

    const int NSTAGE = D_FEAT / 16;
    const int rA = lane >> 2;
    const int cA = lane & 3;

    for (int s = 0; s < NSTAGE; s++) {
        const int cur = s & 1;
        float4 pa0, pa1, pb0, pb1;
        if (s + 1 < NSTAGE) {
            ldA((s + 1) * 16, pa0, pa1);
            ldB((s + 1) * 16, pb0, pb1);
        }

        #pragma unroll
        for (int ks = 0; ks < 2; ks++) {
            const int kk = ks * 8;
            unsigned afr[2][4];
            #pragma unroll
            for (int mt = 0; mt < 2; mt++) {
                const int r = wm * 32 + mt * 16 + rA;
                afr[mt][0] = As[cur][r * PK + kk + cA];
                afr[mt][1] = As[cur][(r + 8) * PK + kk + cA];
                afr[mt][2] = As[cur][r * PK + kk + cA + 4];
                afr[mt][3] = As[cur][(r + 8) * PK + kk + cA + 4];
            }
            #pragma unroll
            for (int nt = 0; nt < 8; nt++) {
                const int n = wn * 64 + nt * 8 + rA;
                const unsigned bfr0 = Bs[cur][(kk + cA) * PN + n];
                const unsigned bfr1 = Bs[cur][(kk + 4 + cA) * PN + n];
                #pragma unroll
                for (int mt = 0; mt < 2; mt++) {
                    asm volatile(
                        "mma.sync.aligned.m16n8k8.row.col.f32.tf32.tf32.f32 "
                        "{%0,%1,%2,%3}, {%4,%5,%6,%7}, {%8,%9}, {%0,%1,%2,%3};"
                        : "+f"(c[mt][nt][0]), "+f"(c[mt][nt][1]),
                          "+f"(c[mt][nt][2]), "+f"(c[mt][nt][3])
                        : "r"(afr[mt][0]), "r"(afr[mt][1]),
                          "r"(afr[mt][2]), "r"(afr[mt][3]),
                          "r"(bfr0), "r"(bfr1));
                }
            }
        }

        if (s + 1 < NSTAGE) {
            stA(cur ^ 1, pa0, pa1);
            stB(cur ^ 1, pb0, pb1);
            __syncthreads();
        }
    }

    // epilogue: c -> g_h1b (bf16 pairs); col is always even
    #pragma unroll
    for (int mt = 0; mt < 2; mt++) {
        const int r_lo = row0 + wm * 32 + mt * 16 + rA;
        const int r_hi = r_lo + 8;
        #pragma unroll
        for (int nt = 0; nt < 8; nt++) {
            const int col = wn * 64 + nt * 8 + 2 * cA;
            if (r_lo < N_NODES)
                g_h1b[(size_t)r_lo * (HIDDEN / 2) + col / 2] =
                    __float22bfloat162_rn(make_float2(c[mt][nt][0], c[mt][nt][1]));
            if (r_hi < N_NODES)
                g_h1b[(size_t)r_hi * (HIDDEN / 2) + col / 2] =
                    __float22bfloat162_rn(make_float2(c[mt][nt][2], c[mt][nt][3]));
        }
    }
}

// ---------------- layer-1 aggregation: bf16 pull gather, warp per node ----------------
// Each lane handles 4 features = 2 bf162 = one uint2 (8B) per source row.
__device__ __forceinline__ void acc_bf16row(float4& acc, float w,
                                            const __nv_bfloat162* rowbase, int lane) {
    const uint2 u = *((const uint2*)rowbase + lane);
    const float2 f0 = __bfloat1622float2(*reinterpret_cast<const __nv_bfloat162*>(&u.x));
    const float2 f1 = __bfloat1622float2(*reinterpret_cast<const __nv_bfloat162*>(&u.y));
    acc.x = fmaf(w, f0.x, acc.x);
    acc.y = fmaf(w, f0.y, acc.y);
    acc.z = fmaf(w, f1.x, acc.z);
    acc.w = fmaf(w, f1.y, acc.w);
}

__global__ void k_gather1(const float* __restrict__ b1) {
    const int node = (blockIdx.x * blockDim.x + threadIdx.x) >> 5;
    const int lane = threadIdx.x & 31;
    if (node >= N_NODES) return;
    const int beg = g_rowptr[node];
    const int end = g_rowptr[node + 1];

    float4 acc = make_float4(0.f, 0.f, 0.f, 0.f);
    int i = beg;
    for (; i + 1 < end; i += 2) {
        const int s0 = g_srcs[i], s1 = g_srcs[i + 1];
        const float w0 = g_dinv[s0], w1 = g_dinv[s1];
        acc_bf16row(acc, w0, g_h1b + (size_t)s0 * (HIDDEN / 2), lane);
        acc_bf16row(acc, w1, g_h1b + (size_t)s1 * (HIDDEN / 2), lane);
    }
    if (i < end) {
        const int s0 = g_srcs[i];
        acc_bf16row(acc, g_dinv[s0], g_h1b + (size_t)s0 * (HIDDEN / 2), lane);
    }

    const float di = g_dinv[node];
    acc_bf16row(acc, di, g_h1b + (size_t)node * (HIDDEN / 2), lane);

    const float4 bb = *(const float4*)(b1 + lane * 4);
    float4 r;
    r.x = fmaxf(fmaf(di, acc.x, bb.x), 0.f);
    r.y = fmaxf(fmaf(di, acc.y, bb.y), 0.f);
    r.z = fmaxf(fmaf(di, acc.z, bb.z), 0.f);
    r.w = fmaxf(fmaf(di, acc.w, bb.w), 0.f);
    *(float4*)(g_agg1 + (size_t)node * HIDDEN + lane * 4) = r;
}

// ---------------- h2 = agg1 @ W2  (warp per node) ----------------
__global__ void k_gemm2(const float* __restrict__ W2) {
    const int node = (blockIdx.x * blockDim.x + threadIdx.x) >> 5;
    const int lane = threadIdx.x & 31;
    if (node >= N_NODES) return;
    float r[4];
    #pragma unroll
    for (int c = 0; c < 4; c++)
        r[c] = g_agg1[(size_t)node * HIDDEN + c * 32 + lane];
    float acc = 0.0f;
    #pragma unroll
    for (int k = 0; k < HIDDEN; k++) {
        const float v = __shfl_sync(0xffffffff, r[k >> 5], k & 31);
        acc = fmaf(v, W2[k * N_CLS + lane], acc);
    }
    g_h2[(size_t)node * N_CLS + lane] = acc;
}

// ---------------- layer-2 aggregation + bias + log-softmax ----------------
__global__ void k_gather2(float* __restrict__ out, const float* __restrict__ b2) {
    const int node = (blockIdx.x * blockDim.x + threadIdx.x) >> 5;
    const int lane = threadIdx.x & 31;
    if (node >= N_NODES) return;
    const int beg = g_rowptr[node];
    const int end = g_rowptr[node + 1];

    float acc = 0.f;
    int i = beg;
    for (; i + 1 < end; i += 2) {
        const int s0 = g_srcs[i], s1 = g_srcs[i + 1];
        const float w0 = g_dinv[s0], w1 = g_dinv[s1];
        acc = fmaf(w0, g_h2[(size_t)s0 * N_CLS + lane], acc);
        acc = fmaf(w1, g_h2[(size_t)s1 * N_CLS + lane], acc);
    }
    if (i < end) {
        const int s0 = g_srcs[i];
        acc = fmaf(g_dinv[s0], g_h2[(size_t)s0 * N_CLS + lane], acc);
    }

    const float di = g_dinv[node];
    acc = fmaf(di, g_h2[(size_t)node * N_CLS + lane], acc);
    float v = fmaf(di, acc, b2[lane]);

    float m = v;
    #pragma unroll
    for (int o = 16; o > 0; o >>= 1)
        m = fmaxf(m, __shfl_xor_sync(0xffffffff, m, o));
    float s = expf(v - m);
    #pragma unroll
    for (int o = 16; o > 0; o >>= 1)
        s += __shfl_xor_sync(0xffffffff, s, o);
    out[(size_t)node * N_CLS + lane] = v - m - logf(s);
}

// ---------------- launcher ----------------
extern "C" void kernel_launch(void* const* d_in, const int* in_sizes, int n_in,
                              void* d_out, int out_size) {
    const float* x  = (const float*)d_in[0];
    const int*   ei = (const int*)d_in[1];    // int32 (jax x64 disabled)
    const float* W1 = (const float*)d_in[2];
    const float* b1 = (const float*)d_in[3];
    const float* W2 = (const float*)d_in[4];
    const float* b2 = (const float*)d_in[5];
    float* out = (float*)d_out;

    const int E = in_sizes[1] / 2;
    const int* src = ei;
    const int* dst = ei + E;

    k_zero_cnt<<<(N_NODES + 255) / 256, 256>>>();
    k_count<<<(E + 255) / 256, 256>>>(dst, E);
    k_scan<<<1, 1024>>>();
    k_fill<<<(E + 255) / 256, 256>>>(src, dst, E);
    k_gemm1_tc<<<(N_NODES + 127) / 128, 256>>>(x, W1);
    k_gather1<<<(N_NODES * 32 + 255) / 256, 256>>>(b1);
    k_gemm2<<<(N_NODES * 32 + 255) / 256, 256>>>(W2);
    k_gather2<<<(N_NODES * 32 + 255) / 256, 256>>>(out, b2);
}

// round 10
// speedup vs baseline: 2.6160x; 1.0005x over previous
#include <cuda_runtime.h>
#include <cuda_bf16.h>
#include <math.h>

#define N_NODES  50000
#define N_EDGES  1600000
#define D_FEAT   512
#define HIDDEN   128
#define N_CLS    32

// ---------------- device scratch (no allocs allowed) ----------------
__device__ __align__(256) int   g_cnt   [N_NODES];        // in-degree, then cursor
__device__ __align__(256) int   g_rowptr[N_NODES + 1];
__device__ __align__(256) float g_dinv  [N_NODES];
__device__ __align__(256) int   g_srcs  [N_EDGES];        // CSR: src per slot (sorted by dst)
__device__ __align__(256) __nv_bfloat162 g_h1b[(size_t)N_NODES * (HIDDEN / 2)]; // x@W1, bf16
__device__ __align__(256) float g_agg1[(size_t)N_NODES * HIDDEN]; // relu(A_hat h1 + b1)
__device__ __align__(256) float g_h2  [(size_t)N_NODES * N_CLS];  // agg1 @ W2

// ---------------- CSR build ----------------

__global__ void k_zero_cnt() {
    int i = blockIdx.x * blockDim.x + threadIdx.x;
    if (i < N_NODES) g_cnt[i] = 0;
}

__global__ void k_count(const int* __restrict__ dst, int E) {
    int e = blockIdx.x * blockDim.x + threadIdx.x;
    if (e < E) atomicAdd(&g_cnt[dst[e]], 1);
}

__global__ __launch_bounds__(1024) void k_scan() {
    __shared__ int sums[1024];
    const int t = threadIdx.x;
    const int CH = (N_NODES + 1023) / 1024;
    const int base = t * CH;
    int local = 0;
    for (int i = 0; i < CH; i++) {
        int idx = base + i;
        if (idx < N_NODES) local += g_cnt[idx];
    }
    sums[t] = local;
    __syncthreads();
    for (int off = 1; off < 1024; off <<= 1) {
        int v = (t >= off) ? sums[t - off] : 0;
        __syncthreads();
        sums[t] += v;
        __syncthreads();
    }
    int run = (t == 0) ? 0 : sums[t - 1];
    for (int i = 0; i < CH; i++) {
        int idx = base + i;
        if (idx < N_NODES) {
            int c = g_cnt[idx];
            g_rowptr[idx] = run;
            run += c;
            g_dinv[idx] = rsqrtf((float)(c + 1));
            g_cnt[idx] = 0;
        }
    }
    if (t == 1023) g_rowptr[N_NODES] = run;
}

__global__ void k_fill(const int* __restrict__ src, const int* __restrict__ dst, int E) {
    int e = blockIdx.x * blockDim.x + threadIdx.x;
    if (e >= E) return;
    int d = dst[e];
    int pos = g_rowptr[d] + atomicAdd(&g_cnt[d], 1);
    g_srcs[pos] = src[e];
}

// ---------------- h1 = x @ W1 via tf32 mma.sync (m16n8k8), bf16 output ----------------
#define PK 20    // A smem row pitch (16 + 4 pad)
#define PN 136   // B smem row pitch (128 + 8 pad)

__device__ __forceinline__ unsigned f2tf32(float f) {
    unsigned r;
    asm("cvt.rna.tf32.f32 %0, %1;" : "=r"(r) : "f"(f));
    return r;
}

__global__ __launch_bounds__(256) void k_gemm1_tc(const float* __restrict__ A,
                                                  const float* __restrict__ B) {
    __shared__ unsigned As[2][128 * PK];
    __shared__ unsigned Bs[2][16 * PN];

    const int tid  = threadIdx.x;
    const int lane = tid & 31;
    const int warp = tid >> 5;
    const int wm = warp >> 1;
    const int wn = warp & 1;
    const int row0 = blockIdx.x * 128;

    float c[2][8][4];
    #pragma unroll
    for (int mt = 0; mt < 2; mt++)
        #pragma unroll
        for (int nt = 0; nt < 8; nt++)
            #pragma unroll
            for (int q = 0; q < 4; q++) c[mt][nt][q] = 0.0f;

    const int af0 = tid, af1 = tid + 256;
    const int bf0 = tid, bf1 = tid + 256;

    auto ldA = [&](int k0, float4& p0, float4& p1) {
        int r0 = af0 >> 2, c40 = af0 & 3;
        int r1 = af1 >> 2, c41 = af1 & 3;
        int gr0 = row0 + r0, gr1 = row0 + r1;
        p0 = (gr0 < N_NODES) ? *(const float4*)(A + (size_t)gr0 * D_FEAT + k0 + c40 * 4)
                             : make_float4(0.f, 0.f, 0.f, 0.f);
        p1 = (gr1 < N_NODES) ? *(const float4*)(A + (size_t)gr1 * D_FEAT + k0 + c41 * 4)
                             : make_float4(0.f, 0.f, 0.f, 0.f);
    };
    auto ldB = [&](int k0, float4& p0, float4& p1) {
        int k_0 = bf0 >> 5, n40 = bf0 & 31;
        int k_1 = bf1 >> 5, n41 = bf1 & 31;
        p0 = *(const float4*)(B + (size_t)(k0 + k_0) * HIDDEN + n40 * 4);
        p1 = *(const float4*)(B + (size_t)(k0 + k_1) * HIDDEN + n41 * 4);
    };
    auto stA = [&](int buf, const float4& p0, const float4& p1) {
        int r0 = af0 >> 2, c40 = af0 & 3;
        int r1 = af1 >> 2, c41 = af1 & 3;
        unsigned* a0 = &As[buf][r0 * PK + c40 * 4];
        a0[0] = f2tf32(p0.x); a0[1] = f2tf32(p0.y); a0[2] = f2tf32(p0.z); a0[3] = f2tf32(p0.w);
        unsigned* a1 = &As[buf][r1 * PK + c41 * 4];
        a1[0] = f2tf32(p1.x); a1[1] = f2tf32(p1.y); a1[2] = f2tf32(p1.z); a1[3] = f2tf32(p1.w);
    };
    auto stB = [&](int buf, const float4& p0, const float4& p1) {
        int k_0 = bf0 >> 5, n40 = bf0 & 31;
        int k_1 = bf1 >> 5, n41 = bf1 & 31;
        unsigned* b0 = &Bs[buf][k_0 * PN + n40 * 4];
        b0[0] = f2tf32(p0.x); b0[1] = f2tf32(p0.y); b0[2] = f2tf32(p0.z); b0[3] = f2tf32(p0.w);
        unsigned* b1 = &Bs[buf][k_1 * PN + n41 * 4];
        b1[0] = f2tf32(p1.x); b1[1] = f2tf32(p1.y); b1[2] = f2tf32(p1.z); b1[3] = f2tf32(p1.w);
    };

    {
        float4 a0, a1, b0, b1;
        ldA(0, a0, a1);
        ldB(0, b0, b1);
        stA(0, a0, a1);
        stB(0, b0, b1);
    }
    __syncthreads();

    const int NSTAGE = D_FEAT / 16;
    const int rA = lane >> 2;
    const int cA = lane & 3;

    for (int s = 0; s < NSTAGE; s++) {
        const int cur = s & 1;
        float4 pa0, pa1, pb0, pb1;
        if (s + 1 < NSTAGE) {
            ldA((s + 1) * 16, pa0, pa1);
            ldB((s + 1) * 16, pb0, pb1);
        }

        #pragma unroll
        for (int ks = 0; ks < 2; ks++) {
            const int kk = ks * 8;
            unsigned afr[2][4];
            #pragma unroll
            for (int mt = 0; mt < 2; mt++) {
                const int r = wm * 32 + mt * 16 + rA;
                afr[mt][0] = As[cur][r * PK + kk + cA];
                afr[mt][1] = As[cur][(r + 8) * PK + kk + cA];
                afr[mt][2] = As[cur][r * PK + kk + cA + 4];
                afr[mt][3] = As[cur][(r + 8) * PK + kk + cA + 4];
            }
            #pragma unroll
            for (int nt = 0; nt < 8; nt++) {
                const int n = wn * 64 + nt * 8 + rA;
                const unsigned bfr0 = Bs[cur][(kk + cA) * PN + n];
                const unsigned bfr1 = Bs[cur][(kk + 4 + cA) * PN + n];
                #pragma unroll
                for (int mt = 0; mt < 2; mt++) {
                    asm volatile(
                        "mma.sync.aligned.m16n8k8.row.col.f32.tf32.tf32.f32 "
                        "{%0,%1,%2,%3}, {%4,%5,%6,%7}, {%8,%9}, {%0,%1,%2,%3};"
                        : "+f"(c[mt][nt][0]), "+f"(c[mt][nt][1]),
                          "+f"(c[mt][nt][2]), "+f"(c[mt][nt][3])
                        : "r"(afr[mt][0]), "r"(afr[mt][1]),
                          "r"(afr[mt][2]), "r"(afr[mt][3]),
                          "r"(bfr0), "r"(bfr1));
                }
            }
        }

        if (s + 1 < NSTAGE) {
            stA(cur ^ 1, pa0, pa1);
            stB(cur ^ 1, pb0, pb1);
            __syncthreads();
        }
    }

    // epilogue: c -> g_h1b (bf16 pairs); col is always even
    #pragma unroll
    for (int mt = 0; mt < 2; mt++) {
        const int r_lo = row0 + wm * 32 + mt * 16 + rA;
        const int r_hi = r_lo + 8;
        #pragma unroll
        for (int nt = 0; nt < 8; nt++) {
            const int col = wn * 64 + nt * 8 + 2 * cA;
            if (r_lo < N_NODES)
                g_h1b[(size_t)r_lo * (HIDDEN / 2) + col / 2] =
                    __float22bfloat162_rn(make_float2(c[mt][nt][0], c[mt][nt][1]));
            if (r_hi < N_NODES)
                g_h1b[(size_t)r_hi * (HIDDEN / 2) + col / 2] =
                    __float22bfloat162_rn(make_float2(c[mt][nt][2], c[mt][nt][3]));
        }
    }
}

// ---------------- layer-1 aggregation: bf16 pull gather, warp per node ----------------
// Batch 8 edges: 8 independent srcs loads, then 8 independent dinv loads,
// then 8 independent 8B row loads -> per-warp MLP ~8 instead of 2.
#define UF 8

__global__ void k_gather1(const float* __restrict__ b1) {
    const int node = (blockIdx.x * blockDim.x + threadIdx.x) >> 5;
    const int lane = threadIdx.x & 31;
    if (node >= N_NODES) return;
    const int beg = g_rowptr[node];
    const int end = g_rowptr[node + 1];

    float4 acc = make_float4(0.f, 0.f, 0.f, 0.f);
    int i = beg;
    for (; i + UF <= end; i += UF) {
        int s[UF];
        #pragma unroll
        for (int j = 0; j < UF; j++) s[j] = g_srcs[i + j];
        float w[UF];
        #pragma unroll
        for (int j = 0; j < UF; j++) w[j] = g_dinv[s[j]];
        uint2 u[UF];
        #pragma unroll
        for (int j = 0; j < UF; j++)
            u[j] = *((const uint2*)(g_h1b + (size_t)s[j] * (HIDDEN / 2)) + lane);
        #pragma unroll
        for (int j = 0; j < UF; j++) {
            const float2 f0 = __bfloat1622float2(*reinterpret_cast<const __nv_bfloat162*>(&u[j].x));
            const float2 f1 = __bfloat1622float2(*reinterpret_cast<const __nv_bfloat162*>(&u[j].y));
            acc.x = fmaf(w[j], f0.x, acc.x);
            acc.y = fmaf(w[j], f0.y, acc.y);
            acc.z = fmaf(w[j], f1.x, acc.z);
            acc.w = fmaf(w[j], f1.y, acc.w);
        }
    }
    for (; i < end; i++) {
        const int s0 = g_srcs[i];
        const float w0 = g_dinv[s0];
        const uint2 u = *((const uint2*)(g_h1b + (size_t)s0 * (HIDDEN / 2)) + lane);
        const float2 f0 = __bfloat1622float2(*reinterpret_cast<const __nv_bfloat162*>(&u.x));
        const float2 f1 = __bfloat1622float2(*reinterpret_cast<const __nv_bfloat162*>(&u.y));
        acc.x = fmaf(w0, f0.x, acc.x);
        acc.y = fmaf(w0, f0.y, acc.y);
        acc.z = fmaf(w0, f1.x, acc.z);
        acc.w = fmaf(w0, f1.y, acc.w);
    }

    const float di = g_dinv[node];
    {
        const uint2 u = *((const uint2*)(g_h1b + (size_t)node * (HIDDEN / 2)) + lane);
        const float2 f0 = __bfloat1622float2(*reinterpret_cast<const __nv_bfloat162*>(&u.x));
        const float2 f1 = __bfloat1622float2(*reinterpret_cast<const __nv_bfloat162*>(&u.y));
        acc.x = fmaf(di, f0.x, acc.x);
        acc.y = fmaf(di, f0.y, acc.y);
        acc.z = fmaf(di, f1.x, acc.z);
        acc.w = fmaf(di, f1.y, acc.w);
    }

    const float4 bb = *(const float4*)(b1 + lane * 4);
    float4 r;
    r.x = fmaxf(fmaf(di, acc.x, bb.x), 0.f);
    r.y = fmaxf(fmaf(di, acc.y, bb.y), 0.f);
    r.z = fmaxf(fmaf(di, acc.z, bb.z), 0.f);
    r.w = fmaxf(fmaf(di, acc.w, bb.w), 0.f);
    *(float4*)(g_agg1 + (size_t)node * HIDDEN + lane * 4) = r;
}

// ---------------- h2 = agg1 @ W2  (warp per node) ----------------
__global__ void k_gemm2(const float* __restrict__ W2) {
    const int node = (blockIdx.x * blockDim.x + threadIdx.x) >> 5;
    const int lane = threadIdx.x & 31;
    if (node >= N_NODES) return;
    float r[4];
    #pragma unroll
    for (int c = 0; c < 4; c++)
        r[c] = g_agg1[(size_t)node * HIDDEN + c * 32 + lane];
    float acc = 0.0f;
    #pragma unroll
    for (int k = 0; k < HIDDEN; k++) {
        const float v = __shfl_sync(0xffffffff, r[k >> 5], k & 31);
        acc = fmaf(v, W2[k * N_CLS + lane], acc);
    }
    g_h2[(size_t)node * N_CLS + lane] = acc;
}

// ---------------- layer-2 aggregation + bias + log-softmax (batched MLP) ----------------
__global__ void k_gather2(float* __restrict__ out, const float* __restrict__ b2) {
    const int node = (blockIdx.x * blockDim.x + threadIdx.x) >> 5;
    const int lane = threadIdx.x & 31;
    if (node >= N_NODES) return;
    const int beg = g_rowptr[node];
    const int end = g_rowptr[node + 1];

    float acc = 0.f;
    int i = beg;
    for (; i + UF <= end; i += UF) {
        int s[UF];
        #pragma unroll
        for (int j = 0; j < UF; j++) s[j] = g_srcs[i + j];
        float w[UF];
        #pragma unroll
        for (int j = 0; j < UF; j++) w[j] = g_dinv[s[j]];
        float v[UF];
        #pragma unroll
        for (int j = 0; j < UF; j++) v[j] = g_h2[(size_t)s[j] * N_CLS + lane];
        #pragma unroll
        for (int j = 0; j < UF; j++) acc = fmaf(w[j], v[j], acc);
    }
    for (; i < end; i++) {
        const int s0 = g_srcs[i];
        acc = fmaf(g_dinv[s0], g_h2[(size_t)s0 * N_CLS + lane], acc);
    }

    const float di = g_dinv[node];
    acc = fmaf(di, g_h2[(size_t)node * N_CLS + lane], acc);
    float v = fmaf(di, acc, b2[lane]);

    float m = v;
    #pragma unroll
    for (int o = 16; o > 0; o >>= 1)
        m = fmaxf(m, __shfl_xor_sync(0xffffffff, m, o));
    float s = expf(v - m);
    #pragma unroll
    for (int o = 16; o > 0; o >>= 1)
        s += __shfl_xor_sync(0xffffffff, s, o);
    out[(size_t)node * N_CLS + lane] = v - m - logf(s);
}

// ---------------- launcher ----------------
extern "C" void kernel_launch(void* const* d_in, const int* in_sizes, int n_in,
                              void* d_out, int out_size) {
    const float* x  = (const float*)d_in[0];
    const int*   ei = (const int*)d_in[1];    // int32 (jax x64 disabled)
    const float* W1 = (const float*)d_in[2];
    const float* b1 = (const float*)d_in[3];
    const float* W2 = (const float*)d_in[4];
    const float* b2 = (const float*)d_in[5];
    float* out = (float*)d_out;

    const int E = in_sizes[1] / 2;
    const int* src = ei;
    const int* dst = ei + E;

    k_zero_cnt<<<(N_NODES + 255) / 256, 256>>>();
    k_count<<<(E + 255) / 256, 256>>>(dst, E);
    k_scan<<<1, 1024>>>();
    k_fill<<<(E + 255) / 256, 256>>>(src, dst, E);
    k_gemm1_tc<<<(N_NODES + 127) / 128, 256>>>(x, W1);
    k_gather1<<<(N_NODES * 32 + 255) / 256, 256>>>(b1);
    k_gemm2<<<(N_NODES * 32 + 255) / 256, 256>>>(W2);
    k_gather2<<<(N_NODES * 32 + 255) / 256, 256>>>(out, b2);
}